// round 4
// baseline (speedup 1.0000x reference)
#include <cuda_runtime.h>
#include <cuda_bf16.h>

#define N      512
#define DIM    256
#define SCAL   10.0f
#define EPSV   1e-12f
#define KLOG2E 14.4269504088896340736f   // SCAL * log2(e)

#define TI   32
#define TJ   64
#define TK   64
#define NBLK 128     // <= 148 SMs -> all CTAs resident in wave 1

__device__ float    g_D[N * N];
__device__ float    g_partial[NBLK];
__device__ float    g_pcount[NBLK];
__device__ unsigned g_bar  = 0;
__device__ unsigned g_done = 0;

__device__ __forceinline__ float ex2a(float x) {
    float y; asm("ex2.approx.ftz.f32 %0, %1;" : "=f"(y) : "f"(x)); return y;
}
__device__ __forceinline__ float rcpa(float x) {
    float y; asm("rcp.approx.ftz.f32 %0, %1;" : "=f"(y) : "f"(x)); return y;
}
__device__ __forceinline__ unsigned ldacq(const unsigned* p) {
    unsigned v;
    asm volatile("ld.acquire.gpu.global.u32 %0, [%1];" : "=r"(v) : "l"(p) : "memory");
    return v;
}

// ---------------------------------------------------------------------------
// Single persistent kernel: dist tiles -> grid barrier -> triplet sums ->
// done-counter -> last block final reduce.
// ---------------------------------------------------------------------------
__global__ void __launch_bounds__(256)
k_fused(const float* __restrict__ feat, const int* __restrict__ y,
        float* __restrict__ out) {
    // phase-1 smem
    __shared__ float As [TI][TK + 4];
    __shared__ float Bst[TK][TJ + 4];
    __shared__ float sqi[TI];
    __shared__ float sqj[TJ];
    // phase-2 smem
    __shared__ float xsh[4][N];          // 4 anchors' scaled D rows
    __shared__ int   ysh[N];
    __shared__ float posR[4][132];
    __shared__ int   npos_s[4], nneg_s[4];
    __shared__ float wsum[8];
    __shared__ float red[128];
    __shared__ int   last_s;

    const int bid  = blockIdx.x;
    const int tid  = threadIdx.x;
    const int warp = tid >> 5;
    const int lane = tid & 31;

    const float4* f4 = reinterpret_cast<const float4*>(feat);  // row pitch 64 f4

    // ======================= PHASE 1: distance tile =======================
    {
        const int i0 = (bid & 15) * TI;
        const int j0 = (bid >> 4) * TJ;
        const int tx = tid & 15;
        const int ty = tid >> 4;

        // squared norms for this tile's rows/cols
        if (tid < 192) {
            const int rid  = tid >> 1;            // 0..95
            const int half = tid & 1;
            const int grow = (rid < TI) ? (i0 + rid) : (j0 + rid - TI);
            float s = 0.f;
            #pragma unroll
            for (int q = 0; q < 32; ++q) {
                float4 v = f4[grow * 64 + half * 32 + q];
                s += v.x * v.x + v.y * v.y + v.z * v.z + v.w * v.w;
            }
            s += __shfl_xor_sync(0xffffffffu, s, 1);
            if (half == 0) {
                if (rid < TI) sqi[rid] = s; else sqj[rid - TI] = s;
            }
        }

        float acc[2][4] = {};

        #pragma unroll
        for (int kc = 0; kc < DIM / TK; ++kc) {
            __syncthreads();
            {   // A tile: 32 rows x 16 f4
                int v = tid;
                #pragma unroll
                for (int s = 0; s < 2; ++s, v += 256) {
                    int i = v >> 4, kq = v & 15;
                    float4 a = f4[(i0 + i) * 64 + kc * 16 + kq];
                    *reinterpret_cast<float4*>(&As[i][4 * kq]) = a;
                }
            }
            {   // B tile transposed: 64 rows x 16 f4
                int v = tid;
                #pragma unroll
                for (int s = 0; s < 4; ++s, v += 256) {
                    int j = v & 63, kq = v >> 6;
                    float4 b = f4[(j0 + j) * 64 + kc * 16 + kq];
                    Bst[4 * kq + 0][j] = b.x;
                    Bst[4 * kq + 1][j] = b.y;
                    Bst[4 * kq + 2][j] = b.z;
                    Bst[4 * kq + 3][j] = b.w;
                }
            }
            __syncthreads();

            #pragma unroll
            for (int k = 0; k < TK; ++k) {
                const float a0 = As[ty * 2 + 0][k];
                const float a1 = As[ty * 2 + 1][k];
                const float4 b = *reinterpret_cast<const float4*>(&Bst[k][tx * 4]);
                acc[0][0] += a0 * b.x; acc[0][1] += a0 * b.y;
                acc[0][2] += a0 * b.z; acc[0][3] += a0 * b.w;
                acc[1][0] += a1 * b.x; acc[1][1] += a1 * b.y;
                acc[1][2] += a1 * b.z; acc[1][3] += a1 * b.w;
            }
        }
        __syncthreads();

        #pragma unroll
        for (int r = 0; r < 2; ++r) {
            const int gi   = i0 + ty * 2 + r;
            const float si = sqi[ty * 2 + r];
            float4 o;
            o.x = sqrtf(fmaxf(si + sqj[tx * 4 + 0] - 2.f * acc[r][0], EPSV));
            o.y = sqrtf(fmaxf(si + sqj[tx * 4 + 1] - 2.f * acc[r][1], EPSV));
            o.z = sqrtf(fmaxf(si + sqj[tx * 4 + 2] - 2.f * acc[r][2], EPSV));
            o.w = sqrtf(fmaxf(si + sqj[tx * 4 + 3] - 2.f * acc[r][3], EPSV));
            *reinterpret_cast<float4*>(&g_D[gi * N + j0 + tx * 4]) = o;
        }
    }

    // ======================= GRID BARRIER =======================
    __threadfence();
    __syncthreads();
    if (tid == 0) {
        atomicAdd(&g_bar, 1u);
        while (ldacq(&g_bar) < NBLK) { }
    }
    __syncthreads();

    // ======================= PHASE 2: 4 anchors per block =======================
    const int abase = bid * 4;

    for (int v = tid; v < N; v += 256) ysh[v] = y[v];
    #pragma unroll
    for (int q = 0; q < 4; ++q) {
        const float* row = &g_D[(abase + q) * N];
        xsh[q][tid]       = row[tid]       * KLOG2E;
        xsh[q][tid + 256] = row[tid + 256] * KLOG2E;
    }
    __syncthreads();

    // warps 0..3 build positive lists for anchors q=warp in parallel
    if (warp < 4) {
        const int   a  = abase + warp;
        const int   ya = ysh[a];
        const float c  = xsh[warp][(a + 1) & (N - 1)];
        int cnt = 0, same = 0;
        for (int base = 0; base < N; base += 32) {
            int  j  = base + lane;
            bool sc = (ysh[j] == ya);
            bool v  = sc && (j != a);
            unsigned mv = __ballot_sync(0xffffffffu, v);
            if (v) {
                int slot = cnt + __popc(mv & ((1u << lane) - 1u));
                posR[warp][slot] = fmaxf(ex2a(c - xsh[warp][j]), 1e-30f);
            }
            cnt  += __popc(mv);
            same += __popc(__ballot_sync(0xffffffffu, sc));
        }
        if (lane == 0) { npos_s[warp] = cnt; nneg_s[warp] = N - same; }
    }
    __syncthreads();

    const float INF = __int_as_float(0x7f800000);
    const int   yn0 = ysh[tid];
    const int   yn1 = ysh[tid + 256];

    float accT = 0.f;
    #pragma unroll
    for (int q = 0; q < 4; ++q) {
        const int   a  = abase + q;
        const int   ya = ysh[a];
        const float c  = xsh[q][(a + 1) & (N - 1)];
        const float e0 = (yn0 != ya) ? ex2a(xsh[q][tid]       - c) : INF;
        const float e1 = (yn1 != ya) ? ex2a(xsh[q][tid + 256] - c) : INF;
        const int npos = npos_s[q];
        float acc = 0.f;
        for (int p = 0; p < npos; ++p) {
            const float rp = posR[q][p];
            acc += rcpa(fmaf(e0, rp, 1.f));
            acc += rcpa(fmaf(e1, rp, 1.f));
        }
        accT += acc;
    }

    #pragma unroll
    for (int o = 16; o > 0; o >>= 1) accT += __shfl_xor_sync(0xffffffffu, accT, o);
    if (lane == 0) wsum[warp] = accT;
    __syncthreads();

    if (tid == 0) {
        float s = 0.f;
        #pragma unroll
        for (int w = 0; w < 8; ++w) s += wsum[w];
        float cc = 0.f;
        #pragma unroll
        for (int q = 0; q < 4; ++q) cc += (float)(npos_s[q] * nneg_s[q]);
        g_partial[bid] = s;
        g_pcount[bid]  = cc;
        __threadfence();
        unsigned t = atomicAdd(&g_done, 1u);
        last_s = (t == NBLK - 1);
    }
    __syncthreads();

    // ======================= FINAL REDUCE (last block) =======================
    if (last_s) {
        __threadfence();
        if (tid < 128) red[tid] = __ldcg(&g_partial[tid]);
        __syncthreads();
        #pragma unroll
        for (int st = 64; st > 0; st >>= 1) {
            if (tid < st) red[tid] += red[tid + st];
            __syncthreads();
        }
        const float tot = red[0];
        __syncthreads();
        if (tid < 128) red[tid] = __ldcg(&g_pcount[tid]);
        __syncthreads();
        #pragma unroll
        for (int st = 64; st > 0; st >>= 1) {
            if (tid < st) red[tid] += red[tid + st];
            __syncthreads();
        }
        if (tid == 0) {
            out[0] = tot / red[0];
            g_bar  = 0;          // reset for next graph replay
            g_done = 0;
        }
    }
}

// ---------------------------------------------------------------------------
extern "C" void kernel_launch(void* const* d_in, const int* in_sizes, int n_in,
                              void* d_out, int out_size) {
    const float* feat = (const float*)d_in[0];
    // d_in[1] = logits (unused by the loss)
    const int*   y    = (const int*)d_in[2];
    float*       out  = (float*)d_out;

    k_fused<<<NBLK, 256>>>(feat, y, out);
}

// round 5
// speedup vs baseline: 1.0013x; 1.0013x over previous
#include <cuda_runtime.h>
#include <cuda_bf16.h>

#define N      512
#define DIM    256
#define SCAL   10.0f
#define EPSV   1e-12f
#define KLOG2E 14.4269504088896340736f   // SCAL * log2(e)

#define TI   32
#define TJ   32
#define TK   64
#define NBLK 256     // 16x16 tile grid; <=2 blocks/SM -> all resident

__device__ float    g_D[N * N];
__device__ float    g_partial[NBLK];
__device__ float    g_pcount[NBLK];
__device__ unsigned g_stripe[16];    // per-stripe producer counters
__device__ unsigned g_done = 0;

__device__ __forceinline__ float ex2a(float x) {
    float y; asm("ex2.approx.ftz.f32 %0, %1;" : "=f"(y) : "f"(x)); return y;
}
__device__ __forceinline__ float rcpa(float x) {
    float y; asm("rcp.approx.ftz.f32 %0, %1;" : "=f"(y) : "f"(x)); return y;
}
__device__ __forceinline__ unsigned ldacq(const unsigned* p) {
    unsigned v;
    asm volatile("ld.acquire.gpu.global.u32 %0, [%1];" : "=r"(v) : "l"(p) : "memory");
    return v;
}

// ---------------------------------------------------------------------------
// One persistent kernel, 256 blocks:
//   phase 1: block bid computes D tile (i0=(bid&15)*32, j0=(bid>>4)*32),
//            then signals stripe counter (bid&15).
//   phase 2: block bid consumes anchors {2*bid, 2*bid+1}; waits only on
//            stripe bid>>4 (16 producers).
//   final:   done-counter; last block reduces 256 partials.
// ---------------------------------------------------------------------------
__global__ void __launch_bounds__(256, 2)
k_fused(const float* __restrict__ feat, const int* __restrict__ y,
        float* __restrict__ out) {
    __shared__ float As [TI][TK + 4];
    __shared__ float Bst[TK][TJ + 4];
    __shared__ float sqi[TI];
    __shared__ float sqj[TJ];
    __shared__ float xsh[2][N];
    __shared__ int   ysh[N];
    __shared__ float posR[2][132];
    __shared__ int   npos_s[2], nneg_s[2];
    __shared__ float wsum[8];
    __shared__ float red[NBLK];
    __shared__ int   last_s;

    const int bid  = blockIdx.x;
    const int tid  = threadIdx.x;
    const int warp = tid >> 5;
    const int lane = tid & 31;

    const float4* f4 = reinterpret_cast<const float4*>(feat);  // row pitch 64 f4

    // ======================= PHASE 1: 32x32 distance tile =======================
    {
        const int i0 = (bid & 15) * TI;
        const int j0 = (bid >> 4) * TJ;
        const int tx = tid & 15;        // 16 cols of float2
        const int ty = tid >> 4;        // 16 rows of 2

        // squared norms: 64 rows, 4 threads/row (16 f4 each)
        {
            const int r = tid >> 2;             // 0..63
            const int q = tid & 3;
            const int grow = (r < TI) ? (i0 + r) : (j0 + r - TI);
            float s = 0.f;
            #pragma unroll
            for (int u = 0; u < 16; ++u) {
                float4 v = f4[grow * 64 + q * 16 + u];
                s += v.x * v.x + v.y * v.y + v.z * v.z + v.w * v.w;
            }
            s += __shfl_xor_sync(0xffffffffu, s, 1);
            s += __shfl_xor_sync(0xffffffffu, s, 2);
            if (q == 0) {
                if (r < TI) sqi[r] = s; else sqj[r - TI] = s;
            }
        }

        float acc00 = 0.f, acc01 = 0.f, acc10 = 0.f, acc11 = 0.f;

        #pragma unroll
        for (int kc = 0; kc < DIM / TK; ++kc) {
            __syncthreads();
            {   // A tile: 32 rows x 16 f4 = 512 f4, 2 per thread
                int v = tid;
                #pragma unroll
                for (int s = 0; s < 2; ++s, v += 256) {
                    int i = v >> 4, kq = v & 15;
                    float4 a = f4[(i0 + i) * 64 + kc * 16 + kq];
                    *reinterpret_cast<float4*>(&As[i][4 * kq]) = a;
                }
            }
            {   // B tile transposed: 32 rows x 16 f4 = 512 f4, 2 per thread
                int v = tid;
                #pragma unroll
                for (int s = 0; s < 2; ++s, v += 256) {
                    int j = v & 31, kq = v >> 5;
                    float4 b = f4[(j0 + j) * 64 + kc * 16 + kq];
                    Bst[4 * kq + 0][j] = b.x;
                    Bst[4 * kq + 1][j] = b.y;
                    Bst[4 * kq + 2][j] = b.z;
                    Bst[4 * kq + 3][j] = b.w;
                }
            }
            __syncthreads();

            #pragma unroll
            for (int k = 0; k < TK; ++k) {
                const float a0 = As[ty * 2 + 0][k];
                const float a1 = As[ty * 2 + 1][k];
                const float2 b = *reinterpret_cast<const float2*>(&Bst[k][tx * 2]);
                acc00 += a0 * b.x; acc01 += a0 * b.y;
                acc10 += a1 * b.x; acc11 += a1 * b.y;
            }
        }

        // epilogue
        {
            const float sj0 = sqj[tx * 2 + 0];
            const float sj1 = sqj[tx * 2 + 1];
            const float si0 = sqi[ty * 2 + 0];
            const float si1 = sqi[ty * 2 + 1];
            float2 o0, o1;
            o0.x = sqrtf(fmaxf(si0 + sj0 - 2.f * acc00, EPSV));
            o0.y = sqrtf(fmaxf(si0 + sj1 - 2.f * acc01, EPSV));
            o1.x = sqrtf(fmaxf(si1 + sj0 - 2.f * acc10, EPSV));
            o1.y = sqrtf(fmaxf(si1 + sj1 - 2.f * acc11, EPSV));
            *reinterpret_cast<float2*>(&g_D[(i0 + ty * 2 + 0) * N + j0 + tx * 2]) = o0;
            *reinterpret_cast<float2*>(&g_D[(i0 + ty * 2 + 1) * N + j0 + tx * 2]) = o1;
        }
    }

    // signal this tile's stripe
    __threadfence();
    __syncthreads();
    if (tid == 0) atomicAdd(&g_stripe[bid & 15], 1u);

    // ======================= wait for anchor stripe =======================
    if (tid == 0) {
        const unsigned* ctr = &g_stripe[bid >> 4];
        while (ldacq(ctr) < 16u) { }
    }
    __syncthreads();

    // ======================= PHASE 2: 2 anchors per block =======================
    const int a0g = bid * 2;

    ysh[tid]       = y[tid];
    ysh[tid + 256] = y[tid + 256];
    {   // load 2 rows (256 f4 total), 1 f4 per thread, scale by KLOG2E
        const int q  = tid >> 7;          // anchor 0/1
        const int c4 = tid & 127;         // f4 col
        const float4* row4 = reinterpret_cast<const float4*>(&g_D[(a0g + q) * N]);
        float4 v = __ldcg(&row4[c4]);
        xsh[q][4 * c4 + 0] = v.x * KLOG2E;
        xsh[q][4 * c4 + 1] = v.y * KLOG2E;
        xsh[q][4 * c4 + 2] = v.z * KLOG2E;
        xsh[q][4 * c4 + 3] = v.w * KLOG2E;
    }
    __syncthreads();

    // warps 0,1 build positive lists for anchors 0,1
    if (warp < 2) {
        const int   a  = a0g + warp;
        const int   ya = ysh[a];
        const float c  = xsh[warp][(a + 1) & (N - 1)];
        int cnt = 0, same = 0;
        for (int base = 0; base < N; base += 32) {
            int  j  = base + lane;
            bool sc = (ysh[j] == ya);
            bool v  = sc && (j != a);
            unsigned mv = __ballot_sync(0xffffffffu, v);
            if (v) {
                int slot = cnt + __popc(mv & ((1u << lane) - 1u));
                posR[warp][slot] = fmaxf(ex2a(c - xsh[warp][j]), 1e-30f);
            }
            cnt  += __popc(mv);
            same += __popc(__ballot_sync(0xffffffffu, sc));
        }
        if (lane == 0) { npos_s[warp] = cnt; nneg_s[warp] = N - same; }
    }
    __syncthreads();

    const float INF = __int_as_float(0x7f800000);
    const int   yn0 = ysh[tid];
    const int   yn1 = ysh[tid + 256];

    float accT = 0.f;
    #pragma unroll
    for (int q = 0; q < 2; ++q) {
        const int   a  = a0g + q;
        const int   ya = ysh[a];
        const float c  = xsh[q][(a + 1) & (N - 1)];
        const float e0 = (yn0 != ya) ? ex2a(xsh[q][tid]       - c) : INF;
        const float e1 = (yn1 != ya) ? ex2a(xsh[q][tid + 256] - c) : INF;
        const int npos = npos_s[q];
        for (int p = 0; p < npos; ++p) {
            const float rp = posR[q][p];
            accT += rcpa(fmaf(e0, rp, 1.f));
            accT += rcpa(fmaf(e1, rp, 1.f));
        }
    }

    #pragma unroll
    for (int o = 16; o > 0; o >>= 1) accT += __shfl_xor_sync(0xffffffffu, accT, o);
    if (lane == 0) wsum[warp] = accT;
    __syncthreads();

    if (tid == 0) {
        float s = 0.f;
        #pragma unroll
        for (int w = 0; w < 8; ++w) s += wsum[w];
        g_partial[bid] = s;
        g_pcount[bid]  = (float)(npos_s[0] * nneg_s[0] + npos_s[1] * nneg_s[1]);
        __threadfence();
        unsigned t = atomicAdd(&g_done, 1u);
        last_s = (t == NBLK - 1);
    }
    __syncthreads();

    // ======================= FINAL REDUCE (last block) =======================
    if (last_s) {
        __threadfence();
        red[tid] = __ldcg(&g_partial[tid]);
        __syncthreads();
        #pragma unroll
        for (int st = 128; st > 0; st >>= 1) {
            if (tid < st) red[tid] += red[tid + st];
            __syncthreads();
        }
        const float tot = red[0];
        __syncthreads();
        red[tid] = __ldcg(&g_pcount[tid]);
        __syncthreads();
        #pragma unroll
        for (int st = 128; st > 0; st >>= 1) {
            if (tid < st) red[tid] += red[tid + st];
            __syncthreads();
        }
        if (tid == 0) {
            out[0] = tot / red[0];
            g_done = 0;                       // reset for next graph replay
        }
        if (tid < 16) g_stripe[tid] = 0;
    }
}

// ---------------------------------------------------------------------------
extern "C" void kernel_launch(void* const* d_in, const int* in_sizes, int n_in,
                              void* d_out, int out_size) {
    const float* feat = (const float*)d_in[0];
    // d_in[1] = logits (unused by the loss)
    const int*   y    = (const int*)d_in[2];
    float*       out  = (float*)d_out;

    k_fused<<<NBLK, 256>>>(feat, y, out);
}